// round 7
// baseline (speedup 1.0000x reference)
#include <cuda_runtime.h>
#include <cuda_bf16.h>
#include <cstdint>
#include <math.h>

// ---------------- problem constants ----------------
#define T_TOK   16384     // B*M = 8*2048
#define FEAT    1024
#define NHEAD   16
#define KD      64

// ---------------- device scratch (no cudaMalloc allowed) ----------------
__device__ __nv_bfloat16 g_x1h[(size_t)T_TOK * FEAT];
__device__ __nv_bfloat16 g_x1l[(size_t)T_TOK * FEAT];
__device__ __nv_bfloat16 g_x2h[(size_t)T_TOK * FEAT];
__device__ __nv_bfloat16 g_x2l[(size_t)T_TOK * FEAT];
__device__ __nv_bfloat16 g_Ohh[(size_t)T_TOK * FEAT];
__device__ __nv_bfloat16 g_Oll[(size_t)T_TOK * FEAT];
__device__ __nv_bfloat16 g_Wqh[(size_t)FEAT * FEAT];
__device__ __nv_bfloat16 g_Wql[(size_t)FEAT * FEAT];
__device__ __nv_bfloat16 g_Wkh[(size_t)FEAT * FEAT];
__device__ __nv_bfloat16 g_Wkl[(size_t)FEAT * FEAT];
__device__ __nv_bfloat16 g_Wvh[(size_t)FEAT * FEAT];
__device__ __nv_bfloat16 g_Wvl[(size_t)FEAT * FEAT];
__device__ __nv_bfloat16 g_Woh[(size_t)FEAT * FEAT];
__device__ __nv_bfloat16 g_Wol[(size_t)FEAT * FEAT];
__device__ float g_Q[(size_t)T_TOK * FEAT];
__device__ float g_K[(size_t)T_TOK * FEAT];
__device__ float g_V[(size_t)T_TOK * FEAT];

// ---------------- low-level helpers (sm_80+ baseline PTX only) ----------------
__device__ __forceinline__ uint32_t smem_u32(const void* p) {
    uint32_t a;
    asm("{ .reg .u64 t; cvta.to.shared.u64 t, %1; cvt.u32.u64 %0, t; }" : "=r"(a) : "l"(p));
    return a;
}
#define CP16(dst, src) \
    asm volatile("cp.async.cg.shared.global [%0], [%1], 16;" :: "r"(dst), "l"(src))
#define CP_COMMIT() asm volatile("cp.async.commit_group;" ::: "memory")
#define CP_WAIT1()  asm volatile("cp.async.wait_group 1;"  ::: "memory")

__device__ __forceinline__ void ldsm4(uint32_t a[4], uint32_t addr) {
    asm volatile("ldmatrix.sync.aligned.m8n8.x4.shared.b16 {%0,%1,%2,%3}, [%4];"
                 : "=r"(a[0]), "=r"(a[1]), "=r"(a[2]), "=r"(a[3]) : "r"(addr));
}
__device__ __forceinline__ void mma16816(float c[4], const uint32_t a[4],
                                         uint32_t b0, uint32_t b1) {
    asm volatile(
        "mma.sync.aligned.m16n8k16.row.col.f32.bf16.bf16.f32 "
        "{%0,%1,%2,%3}, {%4,%5,%6,%7}, {%8,%9}, {%0,%1,%2,%3};"
        : "+f"(c[0]), "+f"(c[1]), "+f"(c[2]), "+f"(c[3])
        : "r"(a[0]), "r"(a[1]), "r"(a[2]), "r"(a[3]), "r"(b0), "r"(b1));
}

// ---------------- fp32 -> bf16 hi/lo split ----------------
__global__ __launch_bounds__(256)
void split_kernel(const float* __restrict__ src, __nv_bfloat16* __restrict__ hi,
                  __nv_bfloat16* __restrict__ lo, int n4) {
    int i = blockIdx.x * blockDim.x + threadIdx.x;
    if (i >= n4) return;
    float4 v = ((const float4*)src)[i];
    __nv_bfloat16 h0 = __float2bfloat16_rn(v.x);
    __nv_bfloat16 h1 = __float2bfloat16_rn(v.y);
    __nv_bfloat16 h2 = __float2bfloat16_rn(v.z);
    __nv_bfloat16 h3 = __float2bfloat16_rn(v.w);
    __nv_bfloat16 l0 = __float2bfloat16_rn(v.x - __bfloat162float(h0));
    __nv_bfloat16 l1 = __float2bfloat16_rn(v.y - __bfloat162float(h1));
    __nv_bfloat16 l2 = __float2bfloat16_rn(v.z - __bfloat162float(h2));
    __nv_bfloat16 l3 = __float2bfloat16_rn(v.w - __bfloat162float(h3));
    ((__nv_bfloat162*)hi)[2 * i]     = __nv_bfloat162(h0, h1);
    ((__nv_bfloat162*)hi)[2 * i + 1] = __nv_bfloat162(h2, h3);
    ((__nv_bfloat162*)lo)[2 * i]     = __nv_bfloat162(l0, l1);
    ((__nv_bfloat162*)lo)[2 * i + 1] = __nv_bfloat162(l2, l3);
}

// ---------------- mma.sync split-bf16 NT GEMM ----------------
// C[M,N] = (Ah+Al)[M,K] * (Bh+Bl)[N,K]^T (+bias), fp32 out.
// CTA tile 128x256, 8 warps as 2(m) x 4(n), warp tile 64x64.
// K staged by 64 bf16, double-buffered cp.async.
#define KC      64
#define ROWB    144                      // 128 data bytes padded to 144
#define A_TILEB (128 * ROWB)             // 18432
#define B_TILEB (256 * ROWB)             // 36864
#define OFF_AL  A_TILEB                  // 18432
#define OFF_BH  (2 * A_TILEB)            // 36864
#define OFF_BL  (2 * A_TILEB + B_TILEB)  // 73728
#define STAGEB  (2 * A_TILEB + 2 * B_TILEB)  // 110592
#define GSMEM   (2 * STAGEB)                 // 221184
#define NSTAGES (FEAT / KC)              // 16

__device__ __forceinline__ void load_stage(
    const __nv_bfloat16* __restrict__ Ah, const __nv_bfloat16* __restrict__ Al,
    const __nv_bfloat16* __restrict__ Bh, const __nv_bfloat16* __restrict__ Bl,
    int m0, int n0, int k0, uint32_t sb, int tid)
{
#pragma unroll
    for (int i = 0; i < 4; i++) {                 // A: 128 rows x 8 chunks
        int idx = i * 256 + tid;
        int row = idx >> 3;
        int ch  = idx & 7;
        uint32_t so = (uint32_t)(row * ROWB + ch * 16);
        size_t ga = (size_t)(m0 + row) * FEAT + k0 + ch * 8;
        CP16(sb + so,          (const char*)(Ah + ga));
        CP16(sb + OFF_AL + so, (const char*)(Al + ga));
    }
#pragma unroll
    for (int i = 0; i < 8; i++) {                 // B: 256 rows x 8 chunks
        int idx = i * 256 + tid;
        int row = idx >> 3;
        int ch  = idx & 7;
        uint32_t so = (uint32_t)(row * ROWB + ch * 16);
        size_t gb = (size_t)(n0 + row) * FEAT + k0 + ch * 8;
        CP16(sb + OFF_BH + so, (const char*)(Bh + gb));
        CP16(sb + OFF_BL + so, (const char*)(Bl + gb));
    }
}

template <bool HAS_BIAS>
__global__ __launch_bounds__(256, 1)
void gemm_tc(const __nv_bfloat16* __restrict__ Ah, const __nv_bfloat16* __restrict__ Al,
             const __nv_bfloat16* __restrict__ Bh, const __nv_bfloat16* __restrict__ Bl,
             const float* __restrict__ bias, float* __restrict__ C)
{
    extern __shared__ char dsm[];
    const int tid  = threadIdx.x;
    const int lane = tid & 31;
    const int wid  = tid >> 5;
    const int wm   = wid & 1;          // m half (64 rows)
    const int wn   = wid >> 1;         // n quarter (64 cols)
    const int m0   = blockIdx.y * 128;
    const int n0   = blockIdx.x * 256;

    const uint32_t smem = smem_u32(dsm);

    const int lrow = lane & 15;
    const int lch  = lane >> 4;
    const uint32_t aoff = (uint32_t)((wm * 64 + lrow) * ROWB + lch * 16);
    const uint32_t boff = (uint32_t)((wn * 64 + lrow) * ROWB + lch * 16);

    float acc[4][8][4];
#pragma unroll
    for (int i = 0; i < 4; i++)
#pragma unroll
        for (int j = 0; j < 8; j++)
#pragma unroll
            for (int q = 0; q < 4; q++) acc[i][j][q] = 0.0f;

    load_stage(Ah, Al, Bh, Bl, m0, n0, 0, smem, tid);
    CP_COMMIT();
    load_stage(Ah, Al, Bh, Bl, m0, n0, KC, smem + STAGEB, tid);
    CP_COMMIT();

    for (int c = 0; c < NSTAGES; c++) {
        CP_WAIT1();
        __syncthreads();

        const uint32_t sb  = smem + (uint32_t)(c & 1) * STAGEB;
        const uint32_t aHi = sb + aoff;
        const uint32_t aLo = sb + OFF_AL + aoff;
        const uint32_t bHi = sb + OFF_BH + boff;
        const uint32_t bLo = sb + OFF_BL + boff;

#pragma unroll
        for (int ks = 0; ks < KC / 16; ks++) {
            const uint32_t ko = (uint32_t)(ks * 32);   // 16 bf16 = 32 B
            uint32_t ah[4][4], al[4][4], bh[4][4], bl[4][4];
#pragma unroll
            for (int mf = 0; mf < 4; mf++) ldsm4(ah[mf], aHi + mf * (16 * ROWB) + ko);
#pragma unroll
            for (int nt = 0; nt < 4; nt++) ldsm4(bh[nt], bHi + nt * (16 * ROWB) + ko);
#pragma unroll
            for (int mf = 0; mf < 4; mf++) ldsm4(al[mf], aLo + mf * (16 * ROWB) + ko);
#pragma unroll
            for (int nt = 0; nt < 4; nt++) ldsm4(bl[nt], bLo + nt * (16 * ROWB) + ko);

#pragma unroll
            for (int mf = 0; mf < 4; mf++)
#pragma unroll
                for (int nt = 0; nt < 4; nt++) {
                    mma16816(acc[mf][nt * 2],     ah[mf], bh[nt][0], bh[nt][2]);
                    mma16816(acc[mf][nt * 2 + 1], ah[mf], bh[nt][1], bh[nt][3]);
                }
#pragma unroll
            for (int mf = 0; mf < 4; mf++)
#pragma unroll
                for (int nt = 0; nt < 4; nt++) {
                    mma16816(acc[mf][nt * 2],     al[mf], bh[nt][0], bh[nt][2]);
                    mma16816(acc[mf][nt * 2 + 1], al[mf], bh[nt][1], bh[nt][3]);
                }
#pragma unroll
            for (int mf = 0; mf < 4; mf++)
#pragma unroll
                for (int nt = 0; nt < 4; nt++) {
                    mma16816(acc[mf][nt * 2],     ah[mf], bl[nt][0], bl[nt][2]);
                    mma16816(acc[mf][nt * 2 + 1], ah[mf], bl[nt][1], bl[nt][3]);
                }
        }

        __syncthreads();
        if (c + 2 < NSTAGES)
            load_stage(Ah, Al, Bh, Bl, m0, n0, (c + 2) * KC,
                       smem + (uint32_t)(c & 1) * STAGEB, tid);
        CP_COMMIT();
    }

    // epilogue
    const int rbase = m0 + wm * 64 + (lane >> 2);
    const int cbase = n0 + wn * 64 + (lane & 3) * 2;
#pragma unroll
    for (int mf = 0; mf < 4; mf++) {
#pragma unroll
        for (int nf = 0; nf < 8; nf++) {
            int r  = rbase + mf * 16;
            int cc = cbase + nf * 8;
            float b0 = 0.f, b1 = 0.f;
            if (HAS_BIAS) { b0 = bias[cc]; b1 = bias[cc + 1]; }
            float* p0 = C + (size_t)r * FEAT + cc;
            p0[0] = acc[mf][nf][0] + b0;
            p0[1] = acc[mf][nf][1] + b1;
            float* p1 = C + (size_t)(r + 8) * FEAT + cc;
            p1[0] = acc[mf][nf][2] + b0;
            p1[1] = acc[mf][nf][3] + b1;
        }
    }
}

// ---------------- per-token attention: 2 tokens per CTA ----------------
// smem layout (floats): Q[2][1024] K[2][1024] V[2][1024] S[2][64*65]
#define ATT_SMEM ((6 * 1024 + 2 * 64 * 65) * 4)

__global__ __launch_bounds__(256)
void attn_kernel(const float* __restrict__ Q,
                 const float* __restrict__ K,
                 const float* __restrict__ V,
                 __nv_bfloat16* __restrict__ Oh,
                 __nv_bfloat16* __restrict__ Ol)
{
    extern __shared__ float sm[];
    float* sQ = sm;                    // 2 x 1024
    float* sK = sm + 2048;             // 2 x 1024
    float* sV = sm + 4096;             // 2 x 1024
    float* sS = sm + 6144;             // 2 x 4160

    const int tid = threadIdx.x;
    const size_t base0 = (size_t)(2 * blockIdx.x) * FEAT;
    const size_t base1 = base0 + FEAT;

    ((float4*)sQ)[tid]        = ((const float4*)(Q + base0))[tid];
    ((float4*)(sQ + 1024))[tid] = ((const float4*)(Q + base1))[tid];
    ((float4*)sK)[tid]        = ((const float4*)(K + base0))[tid];
    ((float4*)(sK + 1024))[tid] = ((const float4*)(K + base1))[tid];
    ((float4*)sV)[tid]        = ((const float4*)(V + base0))[tid];
    ((float4*)(sV + 1024))[tid] = ((const float4*)(V + base1))[tid];
    __syncthreads();

    const int d  = tid & 63;
    const int g4 = tid >> 6;

    // S phase: both tokens interleaved
    {
        float q0[NHEAD], q1[NHEAD];
#pragma unroll
        for (int h = 0; h < NHEAD; h++) {
            q0[h] = sQ[h * 64 + d];
            q1[h] = sQ[1024 + h * 64 + d];
        }
#pragma unroll
        for (int cc = 0; cc < 16; cc++) {
            int c = cc * 4 + g4;
            float s0 = 0.0f, s1 = 0.0f;
#pragma unroll
            for (int h = 0; h < NHEAD; h++) {
                s0 = fmaf(sK[h * 64 + c], q0[h], s0);
                s1 = fmaf(sK[1024 + h * 64 + c], q1[h], s1);
            }
            sS[c * 65 + d]        = s0 * 0.125f;
            sS[4160 + c * 65 + d] = s1 * 0.125f;
        }
    }
    __syncthreads();

    // softmax phase: both tokens interleaved
    {
        const int row = tid >> 2;
        const int j   = tid & 3;
        float* S0 = sS + row * 65;
        float* S1 = sS + 4160 + row * 65;
        float m0 = -1e30f, m1 = -1e30f;
#pragma unroll
        for (int i = 0; i < 16; i++) {
            m0 = fmaxf(m0, S0[j + 4 * i]);
            m1 = fmaxf(m1, S1[j + 4 * i]);
        }
        m0 = fmaxf(m0, __shfl_xor_sync(0xffffffffu, m0, 1));
        m1 = fmaxf(m1, __shfl_xor_sync(0xffffffffu, m1, 1));
        m0 = fmaxf(m0, __shfl_xor_sync(0xffffffffu, m0, 2));
        m1 = fmaxf(m1, __shfl_xor_sync(0xffffffffu, m1, 2));
        float u0 = 0.0f, u1 = 0.0f;
#pragma unroll
        for (int i = 0; i < 16; i++) {
            float e0 = __expf(S0[j + 4 * i] - m0);
            float e1 = __expf(S1[j + 4 * i] - m1);
            S0[j + 4 * i] = e0;
            S1[j + 4 * i] = e1;
            u0 += e0;
            u1 += e1;
        }
        u0 += __shfl_xor_sync(0xffffffffu, u0, 1);
        u1 += __shfl_xor_sync(0xffffffffu, u1, 1);
        u0 += __shfl_xor_sync(0xffffffffu, u0, 2);
        u1 += __shfl_xor_sync(0xffffffffu, u1, 2);
        float i0 = 1.0f / u0, i1 = 1.0f / u1;
#pragma unroll
        for (int i = 0; i < 16; i++) {
            S0[j + 4 * i] *= i0;
            S1[j + 4 * i] *= i1;
        }
    }
    __syncthreads();

    // O phase: both tokens interleaved
    {
        float a0[4] = {0.f, 0.f, 0.f, 0.f};
        float a1[4] = {0.f, 0.f, 0.f, 0.f};
#pragma unroll 8
        for (int v = 0; v < 64; v++) {
            float p0 = sS[v * 65 + d];
            float p1 = sS[4160 + v * 65 + d];
#pragma unroll
            for (int i = 0; i < 4; i++) {
                a0[i] = fmaf(sV[(i * 4 + g4) * 64 + v], p0, a0[i]);
                a1[i] = fmaf(sV[1024 + (i * 4 + g4) * 64 + v], p1, a1[i]);
            }
        }
#pragma unroll
        for (int i = 0; i < 4; i++) {
            size_t off = (size_t)(i * 4 + g4) * 64 + d;
            float x0 = a0[i];
            __nv_bfloat16 h0 = __float2bfloat16_rn(x0);
            Oh[base0 + off] = h0;
            Ol[base0 + off] = __float2bfloat16_rn(x0 - __bfloat162float(h0));
            float x1 = a1[i];
            __nv_bfloat16 h1 = __float2bfloat16_rn(x1);
            Oh[base1 + off] = h1;
            Ol[base1 + off] = __float2bfloat16_rn(x1 - __bfloat162float(h1));
        }
    }
}

// ---------------- launch ----------------
extern "C" void kernel_launch(void* const* d_in, const int* in_sizes, int n_in,
                              void* d_out, int out_size)
{
    const float* x1 = (const float*)d_in[0];
    const float* x2 = (const float*)d_in[1];
    const float* Wq = (const float*)d_in[2];
    const float* Wk = (const float*)d_in[3];
    const float* Wv = (const float*)d_in[4];
    const float* Wo = (const float*)d_in[5];
    const float* bo = (const float*)d_in[6];
    float* out = (float*)d_out;

    __nv_bfloat16 *x1h, *x1l, *x2h, *x2l, *Ohp, *Olp;
    __nv_bfloat16 *Wqh, *Wql, *Wkh, *Wkl, *Wvh, *Wvl, *Woh, *Wol;
    float *Qp, *Kp, *Vp;
    cudaGetSymbolAddress((void**)&x1h, g_x1h);
    cudaGetSymbolAddress((void**)&x1l, g_x1l);
    cudaGetSymbolAddress((void**)&x2h, g_x2h);
    cudaGetSymbolAddress((void**)&x2l, g_x2l);
    cudaGetSymbolAddress((void**)&Ohp, g_Ohh);
    cudaGetSymbolAddress((void**)&Olp, g_Oll);
    cudaGetSymbolAddress((void**)&Wqh, g_Wqh);
    cudaGetSymbolAddress((void**)&Wql, g_Wql);
    cudaGetSymbolAddress((void**)&Wkh, g_Wkh);
    cudaGetSymbolAddress((void**)&Wkl, g_Wkl);
    cudaGetSymbolAddress((void**)&Wvh, g_Wvh);
    cudaGetSymbolAddress((void**)&Wvl, g_Wvl);
    cudaGetSymbolAddress((void**)&Woh, g_Woh);
    cudaGetSymbolAddress((void**)&Wol, g_Wol);
    cudaGetSymbolAddress((void**)&Qp, g_Q);
    cudaGetSymbolAddress((void**)&Kp, g_K);
    cudaGetSymbolAddress((void**)&Vp, g_V);

    cudaFuncSetAttribute(gemm_tc<false>, cudaFuncAttributeMaxDynamicSharedMemorySize, GSMEM);
    cudaFuncSetAttribute(gemm_tc<true>,  cudaFuncAttributeMaxDynamicSharedMemorySize, GSMEM);
    cudaFuncSetAttribute(attn_kernel,    cudaFuncAttributeMaxDynamicSharedMemorySize, ATT_SMEM);

    const int nTok4 = T_TOK * FEAT / 4;
    const int nW4   = FEAT * FEAT / 4;
    split_kernel<<<(nTok4 + 255) / 256, 256>>>(x1, x1h, x1l, nTok4);
    split_kernel<<<(nTok4 + 255) / 256, 256>>>(x2, x2h, x2l, nTok4);
    split_kernel<<<(nW4 + 255) / 256, 256>>>(Wq, Wqh, Wql, nW4);
    split_kernel<<<(nW4 + 255) / 256, 256>>>(Wk, Wkh, Wkl, nW4);
    split_kernel<<<(nW4 + 255) / 256, 256>>>(Wv, Wvh, Wvl, nW4);
    split_kernel<<<(nW4 + 255) / 256, 256>>>(Wo, Woh, Wol, nW4);

    dim3 grid(FEAT / 256, T_TOK / 128);   // (4, 128)
    gemm_tc<false><<<grid, 256, GSMEM>>>(x1h, x1l, Wqh, Wql, nullptr, Qp);
    gemm_tc<false><<<grid, 256, GSMEM>>>(x2h, x2l, Wkh, Wkl, nullptr, Kp);
    gemm_tc<false><<<grid, 256, GSMEM>>>(x2h, x2l, Wvh, Wvl, nullptr, Vp);

    attn_kernel<<<T_TOK / 2, 256, ATT_SMEM>>>(Qp, Kp, Vp, Ohp, Olp);

    gemm_tc<true><<<grid, 256, GSMEM>>>(Ohp, Olp, Woh, Wol, bo, out);
}

// round 14
// speedup vs baseline: 1.0858x; 1.0858x over previous
#include <cuda_runtime.h>
#include <cuda_bf16.h>
#include <cstdint>
#include <math.h>

// ---------------- problem constants ----------------
#define T_TOK   16384     // B*M = 8*2048
#define FEAT    1024
#define NHEAD   16
#define KD      64

// ---------------- device scratch (no cudaMalloc allowed) ----------------
__device__ __nv_bfloat16 g_x1h[(size_t)T_TOK * FEAT];
__device__ __nv_bfloat16 g_x1l[(size_t)T_TOK * FEAT];
__device__ __nv_bfloat16 g_x2h[(size_t)T_TOK * FEAT];
__device__ __nv_bfloat16 g_x2l[(size_t)T_TOK * FEAT];
__device__ __nv_bfloat16 g_Ohh[(size_t)T_TOK * FEAT];
__device__ __nv_bfloat16 g_Oll[(size_t)T_TOK * FEAT];
__device__ __nv_bfloat16 g_Wqh[(size_t)FEAT * FEAT];
__device__ __nv_bfloat16 g_Wql[(size_t)FEAT * FEAT];
__device__ __nv_bfloat16 g_Wkh[(size_t)FEAT * FEAT];
__device__ __nv_bfloat16 g_Wkl[(size_t)FEAT * FEAT];
__device__ __nv_bfloat16 g_Wvh[(size_t)FEAT * FEAT];
__device__ __nv_bfloat16 g_Wvl[(size_t)FEAT * FEAT];
__device__ __nv_bfloat16 g_Woh[(size_t)FEAT * FEAT];
__device__ __nv_bfloat16 g_Wol[(size_t)FEAT * FEAT];
__device__ float g_Q[(size_t)T_TOK * FEAT];
__device__ float g_K[(size_t)T_TOK * FEAT];
__device__ float g_V[(size_t)T_TOK * FEAT];

// ---------------- low-level helpers (sm_80+ baseline PTX only) ----------------
__device__ __forceinline__ uint32_t smem_u32(const void* p) {
    uint32_t a;
    asm("{ .reg .u64 t; cvta.to.shared.u64 t, %1; cvt.u32.u64 %0, t; }" : "=r"(a) : "l"(p));
    return a;
}
#define CP16(dst, src) \
    asm volatile("cp.async.cg.shared.global [%0], [%1], 16;" :: "r"(dst), "l"(src))
#define CP_COMMIT() asm volatile("cp.async.commit_group;" ::: "memory")
#define CP_WAIT2()  asm volatile("cp.async.wait_group 2;"  ::: "memory")

__device__ __forceinline__ void ldsm4(uint32_t a[4], uint32_t addr) {
    asm volatile("ldmatrix.sync.aligned.m8n8.x4.shared.b16 {%0,%1,%2,%3}, [%4];"
                 : "=r"(a[0]), "=r"(a[1]), "=r"(a[2]), "=r"(a[3]) : "r"(addr));
}
__device__ __forceinline__ void mma16816(float c[4], const uint32_t a[4],
                                         uint32_t b0, uint32_t b1) {
    asm volatile(
        "mma.sync.aligned.m16n8k16.row.col.f32.bf16.bf16.f32 "
        "{%0,%1,%2,%3}, {%4,%5,%6,%7}, {%8,%9}, {%0,%1,%2,%3};"
        : "+f"(c[0]), "+f"(c[1]), "+f"(c[2]), "+f"(c[3])
        : "r"(a[0]), "r"(a[1]), "r"(a[2]), "r"(a[3]), "r"(b0), "r"(b1));
}

// ---------------- fp32 -> bf16 hi/lo split ----------------
__device__ __forceinline__ void split_elem4(const float* __restrict__ src,
                                            __nv_bfloat16* __restrict__ hi,
                                            __nv_bfloat16* __restrict__ lo, int i) {
    float4 v = ((const float4*)src)[i];
    __nv_bfloat16 h0 = __float2bfloat16_rn(v.x);
    __nv_bfloat16 h1 = __float2bfloat16_rn(v.y);
    __nv_bfloat16 h2 = __float2bfloat16_rn(v.z);
    __nv_bfloat16 h3 = __float2bfloat16_rn(v.w);
    __nv_bfloat16 l0 = __float2bfloat16_rn(v.x - __bfloat162float(h0));
    __nv_bfloat16 l1 = __float2bfloat16_rn(v.y - __bfloat162float(h1));
    __nv_bfloat16 l2 = __float2bfloat16_rn(v.z - __bfloat162float(h2));
    __nv_bfloat16 l3 = __float2bfloat16_rn(v.w - __bfloat162float(h3));
    ((__nv_bfloat162*)hi)[2 * i]     = __nv_bfloat162(h0, h1);
    ((__nv_bfloat162*)hi)[2 * i + 1] = __nv_bfloat162(h2, h3);
    ((__nv_bfloat162*)lo)[2 * i]     = __nv_bfloat162(l0, l1);
    ((__nv_bfloat162*)lo)[2 * i + 1] = __nv_bfloat162(l2, l3);
}

__global__ __launch_bounds__(256)
void split_kernel(const float* __restrict__ src, __nv_bfloat16* __restrict__ hi,
                  __nv_bfloat16* __restrict__ lo, int n4) {
    int i = blockIdx.x * blockDim.x + threadIdx.x;
    if (i >= n4) return;
    split_elem4(src, hi, lo, i);
}

// Batched: 4 (src,hi,lo) triples selected by blockIdx.y — one launch for all weights.
__global__ __launch_bounds__(256)
void split4_kernel(const float* __restrict__ s0, __nv_bfloat16* __restrict__ h0p, __nv_bfloat16* __restrict__ l0p,
                   const float* __restrict__ s1, __nv_bfloat16* __restrict__ h1p, __nv_bfloat16* __restrict__ l1p,
                   const float* __restrict__ s2, __nv_bfloat16* __restrict__ h2p, __nv_bfloat16* __restrict__ l2p,
                   const float* __restrict__ s3, __nv_bfloat16* __restrict__ h3p, __nv_bfloat16* __restrict__ l3p,
                   int n4) {
    int i = blockIdx.x * blockDim.x + threadIdx.x;
    if (i >= n4) return;
    switch (blockIdx.y) {
        case 0: split_elem4(s0, h0p, l0p, i); break;
        case 1: split_elem4(s1, h1p, l1p, i); break;
        case 2: split_elem4(s2, h2p, l2p, i); break;
        default: split_elem4(s3, h3p, l3p, i); break;
    }
}

// ---------------- mma.sync split-bf16 NT GEMM ----------------
// C[M,N] = (Ah+Al)[M,K] * (Bh+Bl)[N,K]^T (+bias), fp32 out.
// CTA tile 128x128, 8 warps (warp tile 32x64), K staged by 64.
// 3-stage cp.async ring: loads run two stages ahead of compute.
#define KC      64                       // k elements per stage
#define ROWB    144                      // 128 data bytes padded to 144 (9x16B)
#define TILEB   (128 * ROWB)             // 18432 B per matrix tile
#define STAGEB  (4 * TILEB)              // Ah, Al, Bh, Bl = 73728
#define NSTG    3
#define GSMEM   (NSTG * STAGEB)          // 221184 B
#define NSTAGES (FEAT / KC)              // 16

__device__ __forceinline__ void load_stage(
    const __nv_bfloat16* __restrict__ Ah, const __nv_bfloat16* __restrict__ Al,
    const __nv_bfloat16* __restrict__ Bh, const __nv_bfloat16* __restrict__ Bl,
    int m0, int n0, int k0, uint32_t sb, int tid)
{
#pragma unroll
    for (int i = 0; i < 4; i++) {
        int idx = i * 256 + tid;          // 0..1023
        int row = idx >> 3;               // 0..127
        int ch  = idx & 7;                // 16B chunk within 128B row
        uint32_t so = (uint32_t)(row * ROWB + ch * 16);
        size_t ga = (size_t)(m0 + row) * FEAT + k0 + ch * 8;
        size_t gb = (size_t)(n0 + row) * FEAT + k0 + ch * 8;
        CP16(sb + so,              (const char*)(Ah + ga));
        CP16(sb + TILEB + so,      (const char*)(Al + ga));
        CP16(sb + 2 * TILEB + so,  (const char*)(Bh + gb));
        CP16(sb + 3 * TILEB + so,  (const char*)(Bl + gb));
    }
}

template <bool HAS_BIAS>
__global__ __launch_bounds__(256, 1)
void gemm_tc(const __nv_bfloat16* __restrict__ Ah, const __nv_bfloat16* __restrict__ Al,
             const __nv_bfloat16* __restrict__ Bh, const __nv_bfloat16* __restrict__ Bl,
             const float* __restrict__ bias, float* __restrict__ C)
{
    extern __shared__ char dsm[];
    const int tid  = threadIdx.x;
    const int lane = tid & 31;
    const int wid  = tid >> 5;
    const int wm   = wid & 3;          // m block (32 rows)
    const int wn   = wid >> 2;         // n block (64 cols)
    const int m0   = blockIdx.y * 128;
    const int n0   = blockIdx.x * 128;

    const uint32_t smem = smem_u32(dsm);

    const int lrow = lane & 15;
    const int lch  = lane >> 4;
    const uint32_t aoff = (uint32_t)((wm * 32 + lrow) * ROWB + lch * 16);
    const uint32_t boff = (uint32_t)((wn * 64 + lrow) * ROWB + lch * 16);

    float acc[2][8][4];
#pragma unroll
    for (int i = 0; i < 2; i++)
#pragma unroll
        for (int j = 0; j < 8; j++)
#pragma unroll
            for (int q = 0; q < 4; q++) acc[i][j][q] = 0.0f;

    // prologue: stages 0..2
    load_stage(Ah, Al, Bh, Bl, m0, n0, 0 * KC, smem + 0 * STAGEB, tid);
    CP_COMMIT();
    load_stage(Ah, Al, Bh, Bl, m0, n0, 1 * KC, smem + 1 * STAGEB, tid);
    CP_COMMIT();
    load_stage(Ah, Al, Bh, Bl, m0, n0, 2 * KC, smem + 2 * STAGEB, tid);
    CP_COMMIT();

    int buf = 0;
    for (int c = 0; c < NSTAGES; c++) {
        CP_WAIT2();          // stage c resident (2 younger stages may be in flight)
        __syncthreads();

        const uint32_t sb  = smem + (uint32_t)buf * STAGEB;
        const uint32_t aHi = sb + aoff;
        const uint32_t aLo = sb + TILEB + aoff;
        const uint32_t bHi = sb + 2 * TILEB + boff;
        const uint32_t bLo = sb + 3 * TILEB + boff;

#pragma unroll
        for (int ks = 0; ks < KC / 16; ks++) {
            const uint32_t ko = (uint32_t)(ks * 32);   // 16 bf16 = 32 B
            uint32_t ah[2][4], al[2][4], bb[4][4];
#pragma unroll
            for (int mf = 0; mf < 2; mf++) ldsm4(ah[mf], aHi + mf * (16 * ROWB) + ko);
#pragma unroll
            for (int mf = 0; mf < 2; mf++) ldsm4(al[mf], aLo + mf * (16 * ROWB) + ko);
            // B hi: (Ah,Bh) and (Al,Bh)
#pragma unroll
            for (int nt = 0; nt < 4; nt++) ldsm4(bb[nt], bHi + nt * (16 * ROWB) + ko);
#pragma unroll
            for (int mf = 0; mf < 2; mf++)
#pragma unroll
                for (int nt = 0; nt < 4; nt++) {
                    mma16816(acc[mf][nt * 2],     ah[mf], bb[nt][0], bb[nt][2]);
                    mma16816(acc[mf][nt * 2 + 1], ah[mf], bb[nt][1], bb[nt][3]);
                }
#pragma unroll
            for (int mf = 0; mf < 2; mf++)
#pragma unroll
                for (int nt = 0; nt < 4; nt++) {
                    mma16816(acc[mf][nt * 2],     al[mf], bb[nt][0], bb[nt][2]);
                    mma16816(acc[mf][nt * 2 + 1], al[mf], bb[nt][1], bb[nt][3]);
                }
            // B lo: (Ah,Bl)
#pragma unroll
            for (int nt = 0; nt < 4; nt++) ldsm4(bb[nt], bLo + nt * (16 * ROWB) + ko);
#pragma unroll
            for (int mf = 0; mf < 2; mf++)
#pragma unroll
                for (int nt = 0; nt < 4; nt++) {
                    mma16816(acc[mf][nt * 2],     ah[mf], bb[nt][0], bb[nt][2]);
                    mma16816(acc[mf][nt * 2 + 1], ah[mf], bb[nt][1], bb[nt][3]);
                }
        }

        __syncthreads();     // all warps done reading buf before it is overwritten
        if (c + NSTG < NSTAGES)
            load_stage(Ah, Al, Bh, Bl, m0, n0, (c + NSTG) * KC,
                       smem + (uint32_t)buf * STAGEB, tid);
        CP_COMMIT();         // empty group when no load keeps bookkeeping uniform

        buf = (buf + 1 == NSTG) ? 0 : buf + 1;
    }

    // epilogue: direct fp32 stores (2 floats/thread/frag)
    const int rbase = m0 + wm * 32 + (lane >> 2);
    const int cbase = n0 + wn * 64 + (lane & 3) * 2;
#pragma unroll
    for (int mf = 0; mf < 2; mf++) {
#pragma unroll
        for (int nf = 0; nf < 8; nf++) {
            int r = rbase + mf * 16;
            int cc = cbase + nf * 8;
            float b0 = 0.f, b1 = 0.f;
            if (HAS_BIAS) { b0 = bias[cc]; b1 = bias[cc + 1]; }
            float* p0 = C + (size_t)r * FEAT + cc;
            p0[0] = acc[mf][nf][0] + b0;
            p0[1] = acc[mf][nf][1] + b1;
            float* p1 = C + (size_t)(r + 8) * FEAT + cc;
            p1[0] = acc[mf][nf][2] + b0;
            p1[1] = acc[mf][nf][3] + b1;
        }
    }
}

// ---------------- per-token attention (fp32; outputs split bf16) ----------------
__global__ __launch_bounds__(256)
void attn_kernel(const float* __restrict__ Q,
                 const float* __restrict__ K,
                 const float* __restrict__ V,
                 __nv_bfloat16* __restrict__ Oh,
                 __nv_bfloat16* __restrict__ Ol)
{
    __shared__ float sQ[FEAT];
    __shared__ float sK[FEAT];
    __shared__ float sV[FEAT];
    __shared__ float sS[KD * 65];   // padded stride 65: conflict-free softmax

    const int t   = blockIdx.x;
    const int tid = threadIdx.x;
    const size_t base = (size_t)t * FEAT;

    ((float4*)sQ)[tid] = ((const float4*)(Q + base))[tid];
    ((float4*)sK)[tid] = ((const float4*)(K + base))[tid];
    ((float4*)sV)[tid] = ((const float4*)(V + base))[tid];
    __syncthreads();

    const int d  = tid & 63;
    const int g4 = tid >> 6;

    {
        float qreg[NHEAD];
#pragma unroll
        for (int h = 0; h < NHEAD; h++) qreg[h] = sQ[h * 64 + d];
#pragma unroll
        for (int cc = 0; cc < 16; cc++) {
            int c = cc * 4 + g4;
            float s = 0.0f;
#pragma unroll
            for (int h = 0; h < NHEAD; h++)
                s = fmaf(sK[h * 64 + c], qreg[h], s);
            sS[c * 65 + d] = s * 0.125f;
        }
    }
    __syncthreads();

    {
        const int row = tid >> 2;
        const int j   = tid & 3;
        float* Srow = sS + row * 65;
        float mx = -1e30f;
#pragma unroll
        for (int i = 0; i < 16; i++) mx = fmaxf(mx, Srow[j + 4 * i]);
        mx = fmaxf(mx, __shfl_xor_sync(0xffffffffu, mx, 1));
        mx = fmaxf(mx, __shfl_xor_sync(0xffffffffu, mx, 2));
        float sum = 0.0f;
#pragma unroll
        for (int i = 0; i < 16; i++) {
            float e = __expf(Srow[j + 4 * i] - mx);
            Srow[j + 4 * i] = e;
            sum += e;
        }
        sum += __shfl_xor_sync(0xffffffffu, sum, 1);
        sum += __shfl_xor_sync(0xffffffffu, sum, 2);
        float inv = 1.0f / sum;
#pragma unroll
        for (int i = 0; i < 16; i++) Srow[j + 4 * i] *= inv;
    }
    __syncthreads();

    {
        float accv[4] = {0.f, 0.f, 0.f, 0.f};
#pragma unroll 16
        for (int v = 0; v < 64; v++) {
            float p = sS[v * 65 + d];
#pragma unroll
            for (int i = 0; i < 4; i++)
                accv[i] = fmaf(sV[(i * 4 + g4) * 64 + v], p, accv[i]);
        }
#pragma unroll
        for (int i = 0; i < 4; i++) {
            size_t idx = base + (size_t)(i * 4 + g4) * 64 + d;
            float a = accv[i];
            __nv_bfloat16 h = __float2bfloat16_rn(a);
            __nv_bfloat16 l = __float2bfloat16_rn(a - __bfloat162float(h));
            Oh[idx] = h;
            Ol[idx] = l;
        }
    }
}

// ---------------- launch ----------------
extern "C" void kernel_launch(void* const* d_in, const int* in_sizes, int n_in,
                              void* d_out, int out_size)
{
    const float* x1 = (const float*)d_in[0];
    const float* x2 = (const float*)d_in[1];
    const float* Wq = (const float*)d_in[2];
    const float* Wk = (const float*)d_in[3];
    const float* Wv = (const float*)d_in[4];
    const float* Wo = (const float*)d_in[5];
    const float* bo = (const float*)d_in[6];
    float* out = (float*)d_out;

    __nv_bfloat16 *x1h, *x1l, *x2h, *x2l, *Ohp, *Olp;
    __nv_bfloat16 *Wqh, *Wql, *Wkh, *Wkl, *Wvh, *Wvl, *Woh, *Wol;
    float *Qp, *Kp, *Vp;
    cudaGetSymbolAddress((void**)&x1h, g_x1h);
    cudaGetSymbolAddress((void**)&x1l, g_x1l);
    cudaGetSymbolAddress((void**)&x2h, g_x2h);
    cudaGetSymbolAddress((void**)&x2l, g_x2l);
    cudaGetSymbolAddress((void**)&Ohp, g_Ohh);
    cudaGetSymbolAddress((void**)&Olp, g_Oll);
    cudaGetSymbolAddress((void**)&Wqh, g_Wqh);
    cudaGetSymbolAddress((void**)&Wql, g_Wql);
    cudaGetSymbolAddress((void**)&Wkh, g_Wkh);
    cudaGetSymbolAddress((void**)&Wkl, g_Wkl);
    cudaGetSymbolAddress((void**)&Wvh, g_Wvh);
    cudaGetSymbolAddress((void**)&Wvl, g_Wvl);
    cudaGetSymbolAddress((void**)&Woh, g_Woh);
    cudaGetSymbolAddress((void**)&Wol, g_Wol);
    cudaGetSymbolAddress((void**)&Qp, g_Q);
    cudaGetSymbolAddress((void**)&Kp, g_K);
    cudaGetSymbolAddress((void**)&Vp, g_V);

    cudaFuncSetAttribute(gemm_tc<false>, cudaFuncAttributeMaxDynamicSharedMemorySize, GSMEM);
    cudaFuncSetAttribute(gemm_tc<true>,  cudaFuncAttributeMaxDynamicSharedMemorySize, GSMEM);

    const int nTok4 = T_TOK * FEAT / 4;
    const int nW4   = FEAT * FEAT / 4;
    // Launches #1,#2: token splits
    split_kernel<<<(nTok4 + 255) / 256, 256>>>(x1, x1h, x1l, nTok4);
    split_kernel<<<(nTok4 + 255) / 256, 256>>>(x2, x2h, x2l, nTok4);
    // Launch #3: all four weight splits in one grid (blockIdx.y selects weight)
    {
        dim3 g((nW4 + 255) / 256, 4);
        split4_kernel<<<g, 256>>>(Wq, Wqh, Wql,
                                  Wk, Wkh, Wkl,
                                  Wv, Wvh, Wvl,
                                  Wo, Woh, Wol, nW4);
    }

    dim3 grid(FEAT / 128, T_TOK / 128);   // (8, 128)
    // Launches #4,#5,#6 — ncu (-s 5 -c 1) captures launch #6 = gemm_tc (V)
    gemm_tc<false><<<grid, 256, GSMEM>>>(x1h, x1l, Wqh, Wql, nullptr, Qp);
    gemm_tc<false><<<grid, 256, GSMEM>>>(x2h, x2l, Wkh, Wkl, nullptr, Kp);
    gemm_tc<false><<<grid, 256, GSMEM>>>(x2h, x2l, Wvh, Wvl, nullptr, Vp);

    attn_kernel<<<T_TOK, 256>>>(Qp, Kp, Vp, Ohp, Olp);

    gemm_tc<true><<<grid, 256, GSMEM>>>(Ohp, Olp, Woh, Wol, bo, out);
}